// round 14
// baseline (speedup 1.0000x reference)
#include <cuda_runtime.h>

#define K_CODES 16384
#define NSAMP   4096
#define DIM     14
#define HW      1024
#define Q_ELEMS 57344            // 4 * 14 * 1024
#define WPB     8                // warps (= samples) per block, kernel A
#define TBLK    64               // blocks, kernel B
#define TTHR    64               // threads per block, kernel B (64*64 = 4096)

// Module-load zero-initialized; every call restores zeros behind itself so
// each execution (eager correctness run or graph replay) starts identically.
__device__ __align__(16) float g_avg[K_CODES];
__device__ float g_ent_sum;
__device__ float g_hist_sum;
__device__ int   g_done;

__device__ __forceinline__ float warp_sum(float v) {
#pragma unroll
    for (int off = 16; off > 0; off >>= 1)
        v += __shfl_xor_sync(0xffffffffu, v, off);
    return v;
}

// ---------------------------------------------------------------------------
// Kernel A (primary) — IDENTICAL to the measured-best R12 version.
// Entropy + survivor scatter. Fires the PDL trigger AT ENTRY so the
// dependent kernel starts its A-independent work concurrently.
// ONE WARP PER SAMPLE. lane j<14 owns dim j; shuffle reductions give the
// EXACT closed-form entropy (softmax over +-1 codes factorizes per-dim):
//   a_j = 400|xn_j|, logS = sum log(1+e^-a_j), H = logS + sum a_j e_j/(1+e_j)
// Survivor scatter into g_avg: lane = subset mask of dims with a_j < 30
// (dropped probs < e^-30, below fp32 noise).
// ---------------------------------------------------------------------------
__global__ __launch_bounds__(32 * WPB) void lfq_scatter(const float* __restrict__ x) {
    asm volatile("griddepcontrol.launch_dependents;" ::: "memory");

    __shared__ float sc[WPB][DIM];
    __shared__ int   st[WPB][DIM];
    __shared__ float wents[WPB];

    const int wid  = threadIdx.x >> 5;
    const int lane = threadIdx.x & 31;
    const int s    = blockIdx.x * WPB + wid;    // sample id
    const int b    = s >> 10;
    const int n    = s & (HW - 1);

    float v = 0.0f;
    if (lane < DIM) v = x[(b * DIM + lane) * HW + n];

    const float inv = rsqrtf(warp_sum(v * v));

    const unsigned bal = __ballot_sync(0xffffffffu, v > 0.0f) & 0x3FFFu;
    const int idx = (int)(__brev(bal) >> 18);    // big-endian bit order

    const float a = (lane < DIM) ? 400.0f * fabsf(v) * inv : 1e30f;
    const float e = __expf(-a);                  // exactly 0 for pad lanes
    const float logS = warp_sum(__logf(1.0f + e));
    const float ent  = logS + warp_sum(__fdividef(a * e, 1.0f + e));
    if (lane == 0) wents[wid] = ent;

    const bool small = (lane < DIM) && (a < 30.0f);
    const unsigned bm = __ballot_sync(0xffffffffu, small);
    const int m = __popc(bm);
    if (small) {
        const int rank = __popc(bm & ((1u << lane) - 1u));
        sc[wid][rank] = a;
        st[wid][rank] = 1 << (13 - lane);
    }
    __syncwarp();

    const float invS = __expf(-logS);
    const int nm = 1 << m;
    for (int mask = lane; mask < nm; mask += 32) {
        float c = 0.0f;
        int tog = 0;
        for (int j = 0; j < m; j++)
            if ((mask >> j) & 1) { c += sc[wid][j]; tog ^= st[wid][j]; }
        if (c < 30.0f)
            atomicAdd(&g_avg[idx ^ tog], __expf(-c) * invS);
    }

    __syncthreads();
    if (threadIdx.x < WPB) {
        float t = wents[threadIdx.x];
#pragma unroll
        for (int off = WPB / 2; off > 0; off >>= 1)
            t += __shfl_xor_sync((1u << WPB) - 1u, t, off);
        if (threadIdx.x == 0) atomicAdd(&g_ent_sum, t);
    }
}

// ---------------------------------------------------------------------------
// Kernel B (secondary, PDL): starts while A runs. Regridded 64x64 so the
// latency-bound phases spread over 64 SMs instead of 16.
// PRE-WAIT (independent of A): one sample per thread — q = sign(x) writes
//   (coalesced: consecutive threads = consecutive n) + index emit.
// griddepcontrol.wait  (A complete + memflush -> g_avg/g_ent_sum visible)
// POST-WAIT: one float4 histogram chunk per thread, MUFU __logf, zero behind
//   itself; last-ticket block (fence+ticket protocol) writes el, resets state.
// ---------------------------------------------------------------------------
__global__ __launch_bounds__(TTHR) void lfq_tail(const float* __restrict__ x,
                                                 float* __restrict__ out) {
    __shared__ float wsum[TTHR / 32];
    const int tid  = threadIdx.x;
    const int gtid = blockIdx.x * TTHR + tid;    // 0..4095
    const int b    = gtid >> 10;
    const int n    = gtid & (HW - 1);

    // ---- pre-wait: q + index for sample gtid (overlaps with A) ----
    const float* xs = x   + b * DIM * HW + n;
    float*       qo = out + b * DIM * HW + n;
    int idx = 0;
#pragma unroll
    for (int j = 0; j < DIM; j++) {
        const float v = xs[j * HW];
        const bool pos = v > 0.0f;
        qo[j * HW] = pos ? 1.0f : -1.0f;
        if (pos) idx |= (1 << (13 - j));
    }
    out[Q_ELEMS + 1 + gtid] = (float)idx;

    // ---- wait for primary grid (full completion + memory flush) ----
    asm volatile("griddepcontrol.wait;" ::: "memory");

    // ---- post-wait: histogram fold (one float4 per thread) ----
    const float sN = 1.0f / (float)NSAMP;
    float4 a4 = reinterpret_cast<float4*>(g_avg)[gtid];
    reinterpret_cast<float4*>(g_avg)[gtid] = make_float4(0.f, 0.f, 0.f, 0.f);
    float ms = (a4.x * sN) * __logf(a4.x * sN + 1e-9f)
             + (a4.y * sN) * __logf(a4.y * sN + 1e-9f)
             + (a4.z * sN) * __logf(a4.z * sN + 1e-9f)
             + (a4.w * sN) * __logf(a4.w * sN + 1e-9f);

    ms = warp_sum(ms);
    if ((tid & 31) == 0) wsum[tid >> 5] = ms;
    __syncthreads();
    if (tid < TTHR / 32) {
        float t = wsum[tid];
#pragma unroll
        for (int off = TTHR / 64; off > 0; off >>= 1)
            t += __shfl_xor_sync((1u << (TTHR / 32)) - 1u, t, off);
        if (tid == 0) {
            atomicAdd(&g_hist_sum, t);
            __threadfence();
            const int d = atomicAdd(&g_done, 1);
            if (d == TBLK - 1) {
                // all blocks' ent/hist adds happen-before their ticket adds
                const float hs = *(volatile float*)&g_hist_sum;
                const float es = *(volatile float*)&g_ent_sum;
                // el = entro_mean - mean_entro = es/N + sum a*log(a+eps)
                out[Q_ELEMS] = es * (1.0f / (float)NSAMP) + hs;
                g_hist_sum = 0.0f;
                g_ent_sum  = 0.0f;
                g_done     = 0;
            }
        }
    }
}

extern "C" void kernel_launch(void* const* d_in, const int* in_sizes, int n_in,
                              void* d_out, int out_size) {
    const float* x = (const float*)d_in[0];
    float* out = (float*)d_out;

    lfq_scatter<<<NSAMP / WPB, 32 * WPB>>>(x);

    cudaLaunchConfig_t cfg = {};
    cfg.gridDim  = dim3(TBLK);
    cfg.blockDim = dim3(TTHR);
    cfg.stream   = 0;
    cudaLaunchAttribute attr[1];
    attr[0].id = cudaLaunchAttributeProgrammaticStreamSerialization;
    attr[0].val.programmaticStreamSerializationAllowed = 1;
    cfg.attrs    = attr;
    cfg.numAttrs = 1;
    cudaLaunchKernelEx(&cfg, lfq_tail, x, out);
}

// round 15
// speedup vs baseline: 1.2973x; 1.2973x over previous
#include <cuda_runtime.h>

#define K_CODES 16384
#define NSAMP   4096
#define DIM     14
#define HW      1024
#define Q_ELEMS 57344            // 4 * 14 * 1024
#define Q4      (Q_ELEMS / 4)    // 14336 float4 elements
#define WPB     8                // warps (= samples) per block, kernel A
#define TBLK    16               // blocks, kernel B (16*256 = 4096 threads)

// Module-load zero-initialized; every call restores zeros behind itself so
// each execution (eager correctness run or graph replay) starts identically.
__device__ __align__(16) float g_avg[K_CODES];
__device__ float g_ent_sum;
__device__ float g_hist_sum;
__device__ int   g_done;

__device__ __forceinline__ float warp_sum(float v) {
#pragma unroll
    for (int off = 16; off > 0; off >>= 1)
        v += __shfl_xor_sync(0xffffffffu, v, off);
    return v;
}

// ---------------------------------------------------------------------------
// Kernel A (primary): entropy + survivor scatter + index write.
// Fires the PDL trigger AT ENTRY so the dependent kernel starts immediately.
// ONE WARP PER SAMPLE. lane j<14 owns dim j; shuffle reductions give the
// EXACT closed-form entropy (softmax over +-1 codes factorizes per-dim):
//   a_j = 400|xn_j|, logS = sum log(1+e^-a_j), H = logS + sum a_j e_j/(1+e_j)
// Survivor scatter into g_avg: lane = subset mask of dims with a_j < 30
// (dropped probs < e^-30, below fp32 noise). Index = ballot bit-reverse,
// one scalar store per warp.
// ---------------------------------------------------------------------------
__global__ __launch_bounds__(32 * WPB) void lfq_scatter(const float* __restrict__ x,
                                                        float* __restrict__ out) {
    asm volatile("griddepcontrol.launch_dependents;" ::: "memory");

    __shared__ float sc[WPB][DIM];
    __shared__ int   st[WPB][DIM];
    __shared__ float wents[WPB];

    const int wid  = threadIdx.x >> 5;
    const int lane = threadIdx.x & 31;
    const int s    = blockIdx.x * WPB + wid;    // sample id
    const int b    = s >> 10;
    const int n    = s & (HW - 1);

    float v = 0.0f;
    if (lane < DIM) v = x[(b * DIM + lane) * HW + n];

    const float inv = rsqrtf(warp_sum(v * v));

    const unsigned bal = __ballot_sync(0xffffffffu, v > 0.0f) & 0x3FFFu;
    const int idx = (int)(__brev(bal) >> 18);    // big-endian bit order
    if (lane == 0) out[Q_ELEMS + 1 + s] = (float)idx;

    const float a = (lane < DIM) ? 400.0f * fabsf(v) * inv : 1e30f;
    const float e = __expf(-a);                  // exactly 0 for pad lanes
    const float logS = warp_sum(__logf(1.0f + e));
    const float ent  = logS + warp_sum(__fdividef(a * e, 1.0f + e));
    if (lane == 0) wents[wid] = ent;

    const bool small = (lane < DIM) && (a < 30.0f);
    const unsigned bm = __ballot_sync(0xffffffffu, small);
    const int m = __popc(bm);
    if (small) {
        const int rank = __popc(bm & ((1u << lane) - 1u));
        sc[wid][rank] = a;
        st[wid][rank] = 1 << (13 - lane);
    }
    __syncwarp();

    const float invS = __expf(-logS);
    const int nm = 1 << m;
    for (int mask = lane; mask < nm; mask += 32) {
        float c = 0.0f;
        int tog = 0;
        for (int j = 0; j < m; j++)
            if ((mask >> j) & 1) { c += sc[wid][j]; tog ^= st[wid][j]; }
        if (c < 30.0f)
            atomicAdd(&g_avg[idx ^ tog], __expf(-c) * invS);
    }

    __syncthreads();
    if (threadIdx.x < WPB) {
        float t = wents[threadIdx.x];
#pragma unroll
        for (int off = WPB / 2; off > 0; off >>= 1)
            t += __shfl_xor_sync((1u << WPB) - 1u, t, off);
        if (threadIdx.x == 0) atomicAdd(&g_ent_sum, t);
    }
}

// ---------------------------------------------------------------------------
// Kernel B (secondary, PDL): starts while A runs.
// PRE-WAIT (A-independent): pure elementwise q = sign(x), float4-vectorized
//   (14336 float4 over 4096 threads, fully coalesced; no per-sample gathers —
//   the index is written by A).
// griddepcontrol.wait  (A complete + memflush -> g_avg/g_ent_sum visible)
// POST-WAIT: one float4 histogram chunk per thread, MUFU __logf, zero behind
//   itself; last-ticket block (fence+ticket protocol) writes el, resets state.
// ---------------------------------------------------------------------------
__global__ __launch_bounds__(256) void lfq_tail(const float* __restrict__ x,
                                                float* __restrict__ out) {
    __shared__ float wsum[8];
    const int tid  = threadIdx.x;
    const int gtid = blockIdx.x * 256 + tid;     // 0..4095

    // ---- pre-wait: q = sign(x), vectorized (overlaps with A) ----
    const float4* x4 = reinterpret_cast<const float4*>(x);
    float4*       q4 = reinterpret_cast<float4*>(out);
#pragma unroll
    for (int i = gtid; i < Q4; i += 4096) {      // 4 iters, last partial
        float4 xv = x4[i];
        float4 qv;
        qv.x = (xv.x > 0.0f) ? 1.0f : -1.0f;
        qv.y = (xv.y > 0.0f) ? 1.0f : -1.0f;
        qv.z = (xv.z > 0.0f) ? 1.0f : -1.0f;
        qv.w = (xv.w > 0.0f) ? 1.0f : -1.0f;
        q4[i] = qv;
    }

    // ---- wait for primary grid (full completion + memory flush) ----
    asm volatile("griddepcontrol.wait;" ::: "memory");

    // ---- post-wait: histogram fold (one float4 per thread) ----
    const float sN = 1.0f / (float)NSAMP;
    float4 a4 = reinterpret_cast<float4*>(g_avg)[gtid];
    reinterpret_cast<float4*>(g_avg)[gtid] = make_float4(0.f, 0.f, 0.f, 0.f);
    float ms = (a4.x * sN) * __logf(a4.x * sN + 1e-9f)
             + (a4.y * sN) * __logf(a4.y * sN + 1e-9f)
             + (a4.z * sN) * __logf(a4.z * sN + 1e-9f)
             + (a4.w * sN) * __logf(a4.w * sN + 1e-9f);

    ms = warp_sum(ms);
    if ((tid & 31) == 0) wsum[tid >> 5] = ms;
    __syncthreads();
    if (tid < 8) {
        float t = wsum[tid];
#pragma unroll
        for (int off = 4; off > 0; off >>= 1)
            t += __shfl_xor_sync(0xffu, t, off);
        if (tid == 0) {
            atomicAdd(&g_hist_sum, t);
            __threadfence();
            const int d = atomicAdd(&g_done, 1);
            if (d == TBLK - 1) {
                // all blocks' ent/hist adds happen-before their ticket adds
                const float hs = *(volatile float*)&g_hist_sum;
                const float es = *(volatile float*)&g_ent_sum;
                // el = entro_mean - mean_entro = es/N + sum a*log(a+eps)
                out[Q_ELEMS] = es * (1.0f / (float)NSAMP) + hs;
                g_hist_sum = 0.0f;
                g_ent_sum  = 0.0f;
                g_done     = 0;
            }
        }
    }
}

extern "C" void kernel_launch(void* const* d_in, const int* in_sizes, int n_in,
                              void* d_out, int out_size) {
    const float* x = (const float*)d_in[0];
    float* out = (float*)d_out;

    lfq_scatter<<<NSAMP / WPB, 32 * WPB>>>(x, out);

    cudaLaunchConfig_t cfg = {};
    cfg.gridDim  = dim3(TBLK);
    cfg.blockDim = dim3(256);
    cfg.stream   = 0;
    cudaLaunchAttribute attr[1];
    attr[0].id = cudaLaunchAttributeProgrammaticStreamSerialization;
    attr[0].val.programmaticStreamSerializationAllowed = 1;
    cfg.attrs    = attr;
    cfg.numAttrs = 1;
    cudaLaunchKernelEx(&cfg, lfq_tail, x, out);
}

// round 16
// speedup vs baseline: 1.3134x; 1.0124x over previous
#include <cuda_runtime.h>

#define K_CODES 16384
#define NSAMP   4096
#define DIM     14
#define HW      1024
#define Q_ELEMS 57344            // 4 * 14 * 1024
#define Q4      (Q_ELEMS / 4)    // 14336 float4 elements
#define WPB     8                // warps (= samples) per block, kernel A
#define TBLK    16               // blocks, kernel B (16*256 = 4096 threads)

// Module-load zero-initialized; every call restores zeros behind itself so
// each execution (eager correctness run or graph replay) starts identically.
__device__ __align__(16) float g_avg[K_CODES];
__device__ float g_ent_sum;

__device__ __forceinline__ float warp_sum(float v) {
#pragma unroll
    for (int off = 16; off > 0; off >>= 1)
        v += __shfl_xor_sync(0xffffffffu, v, off);
    return v;
}

// ---------------------------------------------------------------------------
// Kernel A (primary) — measured-best family (R12/R15), unchanged:
// entropy + survivor scatter + index write; PDL trigger at entry.
// ONE WARP PER SAMPLE. lane j<14 owns dim j; shuffle reductions give the
// EXACT closed-form entropy (softmax over +-1 codes factorizes per-dim):
//   a_j = 400|xn_j|, logS = sum log(1+e^-a_j), H = logS + sum a_j e_j/(1+e_j)
// Survivor scatter into g_avg: lane = subset mask of dims with a_j < 30
// (dropped probs < e^-30, below fp32 noise).
// ---------------------------------------------------------------------------
__global__ __launch_bounds__(32 * WPB) void lfq_scatter(const float* __restrict__ x,
                                                        float* __restrict__ out) {
    asm volatile("griddepcontrol.launch_dependents;" ::: "memory");

    __shared__ float sc[WPB][DIM];
    __shared__ int   st[WPB][DIM];
    __shared__ float wents[WPB];

    const int wid  = threadIdx.x >> 5;
    const int lane = threadIdx.x & 31;
    const int s    = blockIdx.x * WPB + wid;    // sample id
    const int b    = s >> 10;
    const int n    = s & (HW - 1);

    float v = 0.0f;
    if (lane < DIM) v = x[(b * DIM + lane) * HW + n];

    const float inv = rsqrtf(warp_sum(v * v));

    const unsigned bal = __ballot_sync(0xffffffffu, v > 0.0f) & 0x3FFFu;
    const int idx = (int)(__brev(bal) >> 18);    // big-endian bit order
    if (lane == 0) out[Q_ELEMS + 1 + s] = (float)idx;

    const float a = (lane < DIM) ? 400.0f * fabsf(v) * inv : 1e30f;
    const float e = __expf(-a);                  // exactly 0 for pad lanes
    const float logS = warp_sum(__logf(1.0f + e));
    const float ent  = logS + warp_sum(__fdividef(a * e, 1.0f + e));
    if (lane == 0) wents[wid] = ent;

    const bool small = (lane < DIM) && (a < 30.0f);
    const unsigned bm = __ballot_sync(0xffffffffu, small);
    const int m = __popc(bm);
    if (small) {
        const int rank = __popc(bm & ((1u << lane) - 1u));
        sc[wid][rank] = a;
        st[wid][rank] = 1 << (13 - lane);
    }
    __syncwarp();

    const float invS = __expf(-logS);
    const int nm = 1 << m;
    for (int mask = lane; mask < nm; mask += 32) {
        float c = 0.0f;
        int tog = 0;
        for (int j = 0; j < m; j++)
            if ((mask >> j) & 1) { c += sc[wid][j]; tog ^= st[wid][j]; }
        if (c < 30.0f)
            atomicAdd(&g_avg[idx ^ tog], __expf(-c) * invS);
    }

    __syncthreads();
    if (threadIdx.x < WPB) {
        float t = wents[threadIdx.x];
#pragma unroll
        for (int off = WPB / 2; off > 0; off >>= 1)
            t += __shfl_xor_sync((1u << WPB) - 1u, t, off);
        if (threadIdx.x == 0) atomicAdd(&g_ent_sum, t);
    }
}

// ---------------------------------------------------------------------------
// Kernel B (secondary, PDL): starts while A runs.
// ALL blocks: vectorized q = sign(x) pre-wait work (A-independent).
// Blocks 1..15 then EXIT — no wait, no fence, no tickets.
// Block 0 alone: griddepcontrol.wait (A complete + memflush), then folds the
// ENTIRE 16K-entry histogram (16 float4/thread, MLP-deep, MUFU __logf),
// zeroes it behind itself, reads g_ent_sum with a plain load, writes el,
// resets g_ent_sum. Zero cross-block finalize machinery.
// ---------------------------------------------------------------------------
__global__ __launch_bounds__(256) void lfq_tail(const float* __restrict__ x,
                                                float* __restrict__ out) {
    __shared__ float wsum[8];
    const int tid  = threadIdx.x;
    const int gtid = blockIdx.x * 256 + tid;     // 0..4095

    // ---- pre-wait: q = sign(x), vectorized (overlaps with A) ----
    const float4* x4 = reinterpret_cast<const float4*>(x);
    float4*       q4 = reinterpret_cast<float4*>(out);
#pragma unroll
    for (int i = gtid; i < Q4; i += 4096) {      // 4 iters, last partial
        float4 xv = x4[i];
        float4 qv;
        qv.x = (xv.x > 0.0f) ? 1.0f : -1.0f;
        qv.y = (xv.y > 0.0f) ? 1.0f : -1.0f;
        qv.z = (xv.z > 0.0f) ? 1.0f : -1.0f;
        qv.w = (xv.w > 0.0f) ? 1.0f : -1.0f;
        q4[i] = qv;
    }

    if (blockIdx.x != 0) return;                 // 15 blocks: done, no wait

    // ---- block 0: wait for primary grid (completion + memory flush) ----
    asm volatile("griddepcontrol.wait;" ::: "memory");

    // ---- fold the whole histogram: 16 float4 per thread, deep MLP ----
    const float sN = 1.0f / (float)NSAMP;
    const float4 z4 = make_float4(0.f, 0.f, 0.f, 0.f);
    float ms = 0.0f;
#pragma unroll
    for (int i = 0; i < K_CODES / 4 / 256; i++) {        // 16 iterations
        const int i4 = i * 256 + tid;                    // coalesced
        float4 a4 = reinterpret_cast<float4*>(g_avg)[i4];
        reinterpret_cast<float4*>(g_avg)[i4] = z4;       // restore zeros
        ms += (a4.x * sN) * __logf(a4.x * sN + 1e-9f)
            + (a4.y * sN) * __logf(a4.y * sN + 1e-9f)
            + (a4.z * sN) * __logf(a4.z * sN + 1e-9f)
            + (a4.w * sN) * __logf(a4.w * sN + 1e-9f);
    }

    ms = warp_sum(ms);
    if ((tid & 31) == 0) wsum[tid >> 5] = ms;
    __syncthreads();
    if (tid < 8) {
        float t = wsum[tid];
#pragma unroll
        for (int off = 4; off > 0; off >>= 1)
            t += __shfl_xor_sync(0xffu, t, off);
        if (tid == 0) {
            const float es = g_ent_sum;          // ordered by PDL wait
            // el = entro_mean - mean_entro = es/N + sum a*log(a+eps)
            out[Q_ELEMS] = es * (1.0f / (float)NSAMP) + t;
            g_ent_sum = 0.0f;                    // reset for next replay
        }
    }
}

extern "C" void kernel_launch(void* const* d_in, const int* in_sizes, int n_in,
                              void* d_out, int out_size) {
    const float* x = (const float*)d_in[0];
    float* out = (float*)d_out;

    lfq_scatter<<<NSAMP / WPB, 32 * WPB>>>(x, out);

    cudaLaunchConfig_t cfg = {};
    cfg.gridDim  = dim3(TBLK);
    cfg.blockDim = dim3(256);
    cfg.stream   = 0;
    cudaLaunchAttribute attr[1];
    attr[0].id = cudaLaunchAttributeProgrammaticStreamSerialization;
    attr[0].val.programmaticStreamSerializationAllowed = 1;
    cfg.attrs    = attr;
    cfg.numAttrs = 1;
    cudaLaunchKernelEx(&cfg, lfq_tail, x, out);
}